// round 12
// baseline (speedup 1.0000x reference)
#include <cuda_runtime.h>
#include <cstdint>

#define HID   64
#define CHUNK 128
#define SEQS  8      // sequences per CTA
#define NTHR  128    // thread = (e, kh): 64 elements x 2 k-halves
#define NBLK  128    // 128 * 8 = 1024 sequences

typedef unsigned long long ull;

__device__ __forceinline__ ull pk2(float a, float b) {
    ull r; asm("mov.b64 %0, {%1, %2};" : "=l"(r) : "f"(a), "f"(b)); return r;
}
__device__ __forceinline__ void upk2(ull v, float &a, float &b) {
    asm("mov.b64 {%0, %1}, %2;" : "=f"(a), "=f"(b) : "l"(v));
}
__device__ __forceinline__ ull ffma2(ull a, ull b, ull c) {
    ull d; asm("fma.rn.f32x2 %0, %1, %2, %3;" : "=l"(d) : "l"(a), "l"(b), "l"(c)); return d;
}
// single-MUFU tanh (sm_75+): MUFU.TANH
__device__ __forceinline__ float ftanh_(float x){
    float y; asm("tanh.approx.f32 %0, %1;" : "=f"(y) : "f"(x)); return y;
}
// sigmoid(x) = 0.5*tanh(0.5x) + 0.5
__device__ __forceinline__ float fsig(float x){
    return fmaf(0.5f, ftanh_(0.5f * x), 0.5f);
}

__global__ void pc_zero_kernel(float* o) { if (threadIdx.x == 0) o[0] = 0.0f; }

__global__ void __launch_bounds__(NTHR, 1)
pc_lstm_kernel(const int*   __restrict__ inds,
               const float* __restrict__ p,
               const float* __restrict__ ls_probs,
               const float* __restrict__ open_probs,
               const int*   __restrict__ open_slices,
               const float* __restrict__ open_hx,
               const float* __restrict__ W_ih,
               const float* __restrict__ W_hh,
               const float* __restrict__ b_ih,
               const float* __restrict__ b_hh,
               const float* __restrict__ W_out,
               const float* __restrict__ b_out,
               const int*   __restrict__ n_chunks_ptr,
               float*       __restrict__ out)
{
    __shared__ __align__(16) float hspF[2][SEQS][HID];     // double-buffered h
    __shared__ __align__(16) ull   xsh[SEQS][CHUNK][2];    // splatted (x0,x0),(x1,x1)
    __shared__ float  paysh[SEQS][CHUNK];
    __shared__ float  opwSh[SEQS];
    __shared__ float2 olpSh[SEQS];
    __shared__ int    baseSh[SEQS];

    const int tid  = threadIdx.x;
    const int e    = tid >> 1;        // element 0..63
    const int kh   = tid & 1;         // k-half
    const int kb   = kh * 32;         // k base
    const int kh4  = kh << 2;         // XOR constant: bank-spread iteration order
    const int w    = tid >> 5;        // warp 0..3; handles seqs w and w+4 in phase 4
    const int lane = tid & 31;

    const int rI = e, rF = 64 + e, rG = 128 + e, rO = 192 + e;

    // ---- W_hh: 4 rows x 32 k-values (k-half), k-pair packed = 128 regs ----
    ull wI[16], wF[16], wG[16], wO[16];
    #pragma unroll
    for (int i = 0; i < 8; ++i) {
        int kf = kb + 4 * (i ^ kh4);
        wI[2*i]   = pk2(W_hh[rI * HID + kf],     W_hh[rI * HID + kf + 1]);
        wI[2*i+1] = pk2(W_hh[rI * HID + kf + 2], W_hh[rI * HID + kf + 3]);
        wF[2*i]   = pk2(W_hh[rF * HID + kf],     W_hh[rF * HID + kf + 1]);
        wF[2*i+1] = pk2(W_hh[rF * HID + kf + 2], W_hh[rF * HID + kf + 3]);
        wG[2*i]   = pk2(W_hh[rG * HID + kf],     W_hh[rG * HID + kf + 1]);
        wG[2*i+1] = pk2(W_hh[rG * HID + kf + 2], W_hh[rG * HID + kf + 3]);
        wO[2*i]   = pk2(W_hh[rO * HID + kf],     W_hh[rO * HID + kf + 1]);
        wO[2*i+1] = pk2(W_hh[rO * HID + kf + 2], W_hh[rO * HID + kf + 3]);
    }

    const ull biasIF = pk2(b_ih[rI] + b_hh[rI], b_ih[rF] + b_hh[rF]);
    const ull biasGO = pk2(b_ih[rG] + b_hh[rG], b_ih[rO] + b_hh[rO]);
    const ull wIF0 = pk2(W_ih[rI*2],   W_ih[rF*2]);
    const ull wIF1 = pk2(W_ih[rI*2+1], W_ih[rF*2+1]);
    const ull wGO0 = pk2(W_ih[rG*2],   W_ih[rO*2]);
    const ull wGO1 = pk2(W_ih[rG*2+1], W_ih[rO*2+1]);

    const float wo0 = W_out[2 * lane];
    const float wo1 = W_out[2 * lane + 1];
    const float bo  = b_out[0];

    if (tid < SEQS) {
        int q = blockIdx.x * SEQS + tid;
        baseSh[tid] = inds[q >> 4] + (q & 15);   // B2 == 16
        int sl = open_slices[q];
        olpSh[tid] = make_float2(__logf(p[2 * sl]), __logf(p[2 * sl + 1]));
        opwSh[tid] = open_probs[q] * (2.0f * ls_probs[q] - 1.0f);
    }

    // init c (both kh threads, identical) and h (kh==0 publishes)
    float cc[SEQS];
    #pragma unroll
    for (int s = 0; s < SEQS; ++s) {
        int q = blockIdx.x * SEQS + s;
        cc[s] = open_hx[(q * 2 + 1) * HID + e];
        if (!kh) hspF[0][s][e] = open_hx[(q * 2 + 0) * HID + e];
    }
    __syncthreads();

    const int nch = n_chunks_ptr ? n_chunks_ptr[0] : 128;

    float  nd0 = 1.0f, nd1 = 1.0f;   // survival chains for seqs w and w+4
    double lossAcc = 0.0;
    int    cur = 0;                  // even #steps/chunk -> cur==0 at chunk starts

    for (int ch = 0; ch < nch; ++ch) {
        __syncthreads();  // previous chunk's xsh/paysh fully consumed
        // ---- chunk preamble ----
        for (int i = tid; i < SEQS * CHUNK; i += NTHR) {
            int s  = i >> 7;
            int tt = i & (CHUNK - 1);
            int b  = baseSh[s] + ch * CHUNK;
            float2 pv = ((const float2*)p)[b + tt];
            float2 pz = ((const float2*)p)[b];
            float x0 = pv.x - pz.x, x1 = pv.y - pz.y;
            xsh[s][tt][0] = pk2(x0, x0);
            xsh[s][tt][1] = pk2(x1, x1);
            paysh[s][tt] = opwSh[s] * ((__logf(pv.x) - olpSh[s].x) + (__logf(pv.y) - olpSh[s].y));
        }
        __syncthreads();

        #pragma unroll 1
        for (int t = 0; t < CHUNK; ++t) {
            // ---- lagged phase-4 h reads (h after step t-1), seqs w and w+4 ----
            float2 hv0, hv1;
            if (t) {
                hv0 = ((const float2*)hspF[cur][w])[lane];
                hv1 = ((const float2*)hspF[cur][w + 4])[lane];
            }

            // ---- matvec: 4 rows x k-half x 8 seqs; 1 LDS.128 -> 8 FFMA2 ----
            ull accI[SEQS], accF[SEQS], accG[SEQS], accO[SEQS];
            #pragma unroll
            for (int s = 0; s < SEQS; ++s) { accI[s]=0; accF[s]=0; accG[s]=0; accO[s]=0; }
            #pragma unroll
            for (int i = 0; i < 8; ++i) {
                int kf = kb + 4 * (i ^ kh4);     // bank-spread order for kh=1
                #pragma unroll
                for (int s = 0; s < SEQS; ++s) {
                    ulonglong2 hh = *(const ulonglong2*)&hspF[cur][s][kf];
                    accI[s] = ffma2(wI[2*i], hh.x, accI[s]);
                    accF[s] = ffma2(wF[2*i], hh.x, accF[s]);
                    accG[s] = ffma2(wG[2*i], hh.x, accG[s]);
                    accO[s] = ffma2(wO[2*i], hh.x, accO[s]);
                    accI[s] = ffma2(wI[2*i+1], hh.y, accI[s]);
                    accF[s] = ffma2(wF[2*i+1], hh.y, accF[s]);
                    accG[s] = ffma2(wG[2*i+1], hh.y, accG[s]);
                    accO[s] = ffma2(wO[2*i+1], hh.y, accO[s]);
                }
            }

            // ---- lagged phase 4 (step t-1): 2 seqs per warp, overlaps FMA stream ----
            if (t) {
                float part0 = fmaf(hv0.x, wo0, hv0.y * wo1);
                float part1 = fmaf(hv1.x, wo0, hv1.y * wo1);
                #pragma unroll
                for (int o = 16; o; o >>= 1) {
                    part0 += __shfl_xor_sync(0xffffffffu, part0, o);
                    part1 += __shfl_xor_sync(0xffffffffu, part1, o);
                }
                float raw0 = fsig(part0 + bo);
                float raw1 = fsig(part1 + bo);
                float pay0 = paysh[w][t - 1];
                float pay1 = paysh[w + 4][t - 1];
                float adj0 = (t - 1 == 0) ? raw0 : raw0 * nd0;
                float adj1 = (t - 1 == 0) ? raw1 : raw1 * nd1;
                lossAcc += (double)(adj0 * pay0) + (double)(adj1 * pay1);
                nd0 *= (1.0f - raw0);        // t-1 <= 126: always update
                nd1 *= (1.0f - raw1);
            }

            // ---- fold, k-half combine, split-MUFU gates, c/h update ----
            #pragma unroll
            for (int s = 0; s < SEQS; ++s) {
                ulonglong2 xv = *(const ulonglong2*)&xsh[s][t][0];
                ull aIF = ffma2(wIF1, xv.y, ffma2(wIF0, xv.x, biasIF));
                ull aGO = ffma2(wGO1, xv.y, ffma2(wGO0, xv.x, biasGO));

                float lo, hi;
                upk2(accI[s], lo, hi); float fIv = lo + hi;
                upk2(accF[s], lo, hi); float fFv = lo + hi;
                upk2(accG[s], lo, hi); float fGv = lo + hi;
                upk2(accO[s], lo, hi); float fOv = lo + hi;
                fIv += __shfl_xor_sync(0xffffffffu, fIv, 1);   // combine k-halves
                fFv += __shfl_xor_sync(0xffffffffu, fFv, 1);
                fGv += __shfl_xor_sync(0xffffffffu, fGv, 1);
                fOv += __shfl_xor_sync(0xffffffffu, fOv, 1);
                float inI, inF, inG, inO;
                upk2(aIF, inI, inF);
                upk2(aGO, inG, inO);
                float pI = fIv + inI, pF = fFv + inF;
                float pG = fGv + inG, pO = fOv + inO;

                // split MUFU across the kh pair (all via MUFU.TANH):
                // kh0 computes si, sf ; kh1 computes tg, so ; exchange 2 values
                float u1 = kh ? pG : 0.5f * pI;
                float r1 = ftanh_(u1);
                float g1 = kh ? r1 : fmaf(0.5f, r1, 0.5f);     // kh0: si, kh1: tg
                float u2 = 0.5f * (kh ? pO : pF);
                float g2 = fmaf(0.5f, ftanh_(u2), 0.5f);       // kh0: sf, kh1: so
                float x1 = __shfl_xor_sync(0xffffffffu, g1, 1);
                float x2 = __shfl_xor_sync(0xffffffffu, g2, 1);
                float si = kh ? x1 : g1;
                float tg = kh ? g1 : x1;
                float sf = kh ? x2 : g2;
                float so = kh ? g2 : x2;
                cc[s] = sf * cc[s] + si * tg;
                if (!kh) hspF[cur ^ 1][s][e] = so * ftanh_(cc[s]);
            }
            __syncthreads();   // single barrier: h published, buffers rotate
            cur ^= 1;
        }

        // ---- trailing phase 4 for t = CHUNK-1 (2 seqs per warp) ----
        {
            float2 hv0 = ((const float2*)hspF[cur][w])[lane];
            float2 hv1 = ((const float2*)hspF[cur][w + 4])[lane];
            float part0 = fmaf(hv0.x, wo0, hv0.y * wo1);
            float part1 = fmaf(hv1.x, wo0, hv1.y * wo1);
            #pragma unroll
            for (int o = 16; o; o >>= 1) {
                part0 += __shfl_xor_sync(0xffffffffu, part0, o);
                part1 += __shfl_xor_sync(0xffffffffu, part1, o);
            }
            float raw0 = fsig(part0 + bo);
            float raw1 = fsig(part1 + bo);
            lossAcc += (double)(raw0 * nd0 * paysh[w][CHUNK - 1])
                     + (double)(raw1 * nd1 * paysh[w + 4][CHUNK - 1]);
            // last element of chunk: nd NOT updated (cumprod over [:-1])
        }
    }

    if (lane == 0) atomicAdd(out, (float)lossAcc);
}

extern "C" void kernel_launch(void* const* d_in, const int* in_sizes, int n_in,
                              void* d_out, int out_size)
{
    const int*   inds        = (const int*)  d_in[0];
    const float* p           = (const float*)d_in[1];
    const float* ls_probs    = (const float*)d_in[2];
    const float* open_probs  = (const float*)d_in[3];
    const int*   open_slices = (const int*)  d_in[4];
    const float* open_hx     = (const float*)d_in[5];
    const float* W_ih        = (const float*)d_in[6];
    const float* W_hh        = (const float*)d_in[7];
    const float* b_ih        = (const float*)d_in[8];
    const float* b_hh        = (const float*)d_in[9];
    const float* W_out       = (const float*)d_in[10];
    const float* b_out       = (const float*)d_in[11];
    const int*   n_chunks    = (n_in > 12) ? (const int*)d_in[12] : nullptr;

    float* out = (float*)d_out;

    pc_zero_kernel<<<1, 32>>>(out);
    pc_lstm_kernel<<<NBLK, NTHR>>>(inds, p, ls_probs, open_probs, open_slices,
                                   open_hx, W_ih, W_hh, b_ih, b_hh,
                                   W_out, b_out, n_chunks, out);
}

// round 13
// speedup vs baseline: 1.1889x; 1.1889x over previous
#include <cuda_runtime.h>
#include <cstdint>

#define HID   64
#define CHUNK 128
#define SEQS  4      // sequences per CTA, pairs A={0,1}, B={2,3}
#define NTHR  128    // thread = (e, kh)
#define NBLK  256    // 256 * 4 = 1024 sequences

typedef unsigned long long ull;

__device__ __forceinline__ ull pk2(float a, float b) {
    ull r; asm("mov.b64 %0, {%1, %2};" : "=l"(r) : "f"(a), "f"(b)); return r;
}
__device__ __forceinline__ void upk2(ull v, float &a, float &b) {
    asm("mov.b64 {%0, %1}, %2;" : "=f"(a), "=f"(b) : "l"(v));
}
__device__ __forceinline__ ull ffma2(ull a, ull b, ull c) {
    ull d; asm("fma.rn.f32x2 %0, %1, %2, %3;" : "=l"(d) : "l"(a), "l"(b), "l"(c)); return d;
}
__device__ __forceinline__ float ftanh_(float x){
    float y; asm("tanh.approx.f32 %0, %1;" : "=f"(y) : "f"(x)); return y;
}
__device__ __forceinline__ float fsig(float x){
    return fmaf(0.5f, ftanh_(0.5f * x), 0.5f);
}

__global__ void pc_zero_kernel(float* o) { if (threadIdx.x == 0) o[0] = 0.0f; }

__global__ void __launch_bounds__(NTHR, 2)
pc_lstm_kernel(const int*   __restrict__ inds,
               const float* __restrict__ p,
               const float* __restrict__ ls_probs,
               const float* __restrict__ open_probs,
               const int*   __restrict__ open_slices,
               const float* __restrict__ open_hx,
               const float* __restrict__ W_ih,
               const float* __restrict__ W_hh,
               const float* __restrict__ b_ih,
               const float* __restrict__ b_hh,
               const float* __restrict__ W_out,
               const float* __restrict__ b_out,
               const int*   __restrict__ n_chunks_ptr,
               float*       __restrict__ out)
{
    __shared__ __align__(16) float hspF[SEQS][HID];        // single-buffered h
    __shared__ __align__(16) ull   xsh[SEQS][CHUNK][2];    // splatted (x0,x0),(x1,x1)
    __shared__ float  paysh[SEQS][CHUNK];
    __shared__ float  opwSh[SEQS];
    __shared__ float2 olpSh[SEQS];
    __shared__ int    baseSh[SEQS];

    const int tid   = threadIdx.x;
    const int e     = tid >> 1;       // element 0..63
    const int kh    = tid & 1;        // k-half
    const int kb    = kh * 32;
    const int kh4   = kh << 2;        // bank-spread XOR
    const int w     = tid >> 5;       // warp 0..3 <-> seq w in phase 4
    const int lane  = tid & 31;
    const int wpair = w >> 1;         // 0: pair A seqs {0,1}; 1: pair B seqs {2,3}

    const int rI = e, rF = 64 + e, rG = 128 + e, rO = 192 + e;

    // ---- W_hh: 4 rows x 32 k-values (k-half), k-pair packed, bank-spread ----
    ull wI[16], wF[16], wG[16], wO[16];
    #pragma unroll
    for (int i = 0; i < 8; ++i) {
        int kf = kb + 4 * (i ^ kh4);
        wI[2*i]   = pk2(W_hh[rI * HID + kf],     W_hh[rI * HID + kf + 1]);
        wI[2*i+1] = pk2(W_hh[rI * HID + kf + 2], W_hh[rI * HID + kf + 3]);
        wF[2*i]   = pk2(W_hh[rF * HID + kf],     W_hh[rF * HID + kf + 1]);
        wF[2*i+1] = pk2(W_hh[rF * HID + kf + 2], W_hh[rF * HID + kf + 3]);
        wG[2*i]   = pk2(W_hh[rG * HID + kf],     W_hh[rG * HID + kf + 1]);
        wG[2*i+1] = pk2(W_hh[rG * HID + kf + 2], W_hh[rG * HID + kf + 3]);
        wO[2*i]   = pk2(W_hh[rO * HID + kf],     W_hh[rO * HID + kf + 1]);
        wO[2*i+1] = pk2(W_hh[rO * HID + kf + 2], W_hh[rO * HID + kf + 3]);
    }

    // own-gate input constants: kh0 owns rows (I,F), kh1 owns (G,O)
    const int rowX = kh ? rG : rI;
    const int rowY = kh ? rO : rF;
    const ull biasOwn = pk2(b_ih[rowX] + b_hh[rowX], b_ih[rowY] + b_hh[rowY]);
    const ull wOwn0   = pk2(W_ih[rowX * 2],     W_ih[rowY * 2]);
    const ull wOwn1   = pk2(W_ih[rowX * 2 + 1], W_ih[rowY * 2 + 1]);
    // activation constants: y1 = my1*tanh(m1*p1)+a1  (kh0: sigmoid(I); kh1: tanh(G))
    const float m1  = kh ? 1.0f : 0.5f;
    const float my1 = kh ? 1.0f : 0.5f;
    const float a1  = kh ? 0.0f : 0.5f;

    const float wo0 = W_out[2 * lane];
    const float wo1 = W_out[2 * lane + 1];
    const float bo  = b_out[0];

    if (tid < SEQS) {
        int q = blockIdx.x * SEQS + tid;
        baseSh[tid] = inds[q >> 4] + (q & 15);   // B2 == 16
        int sl = open_slices[q];
        olpSh[tid] = make_float2(__logf(p[2 * sl]), __logf(p[2 * sl + 1]));
        opwSh[tid] = open_probs[q] * (2.0f * ls_probs[q] - 1.0f);
    }

    // init c (valid on kh0) and h (kh0 publishes)
    float cc[SEQS];
    #pragma unroll
    for (int s = 0; s < SEQS; ++s) {
        int q = blockIdx.x * SEQS + s;
        cc[s] = open_hx[(q * 2 + 1) * HID + e];
        if (!kh) hspF[s][e] = open_hx[(q * 2 + 0) * HID + e];
    }
    __syncthreads();

    const int nch = n_chunks_ptr ? n_chunks_ptr[0] : 128;

    float  nd = 1.0f;            // survival chain: warp w <-> seq w
    double lossAcc = 0.0;

    ull accA[4][2], accB[4][2];  // [gate][seq-in-pair]

#define MATVEC(ACC, PB) do {                                                    \
    _Pragma("unroll")                                                           \
    for (int g = 0; g < 4; ++g) { ACC[g][0] = 0ull; ACC[g][1] = 0ull; }         \
    _Pragma("unroll")                                                           \
    for (int i = 0; i < 8; ++i) {                                               \
        int kf = kb + 4 * (i ^ kh4);                                            \
        _Pragma("unroll")                                                       \
        for (int j = 0; j < 2; ++j) {                                           \
            ulonglong2 hh = *(const ulonglong2*)&hspF[(PB) + j][kf];            \
            ACC[0][j] = ffma2(wI[2*i],   hh.x, ACC[0][j]);                      \
            ACC[1][j] = ffma2(wF[2*i],   hh.x, ACC[1][j]);                      \
            ACC[2][j] = ffma2(wG[2*i],   hh.x, ACC[2][j]);                      \
            ACC[3][j] = ffma2(wO[2*i],   hh.x, ACC[3][j]);                      \
            ACC[0][j] = ffma2(wI[2*i+1], hh.y, ACC[0][j]);                      \
            ACC[1][j] = ffma2(wF[2*i+1], hh.y, ACC[1][j]);                      \
            ACC[2][j] = ffma2(wG[2*i+1], hh.y, ACC[2][j]);                      \
            ACC[3][j] = ffma2(wO[2*i+1], hh.y, ACC[3][j]);                      \
        }                                                                       \
    }                                                                           \
} while (0)

#define GATES(ACC, PB, T) do {                                                  \
    _Pragma("unroll")                                                           \
    for (int j = 0; j < 2; ++j) {                                               \
        int s = (PB) + j;                                                       \
        ulonglong2 xv = *(const ulonglong2*)&xsh[s][T][0];                      \
        ull aOwn = ffma2(wOwn1, xv.y, ffma2(wOwn0, xv.x, biasOwn));             \
        float in1, in2; upk2(aOwn, in1, in2);                                   \
        float lo, hi;                                                           \
        upk2(ACC[0][j], lo, hi); float fI = lo + hi;                            \
        upk2(ACC[1][j], lo, hi); float fF = lo + hi;                            \
        upk2(ACC[2][j], lo, hi); float fG = lo + hi;                            \
        upk2(ACC[3][j], lo, hi); float fO = lo + hi;                            \
        float v  = kh ? fI : fG;                                                \
        float vr = __shfl_xor_sync(0xffffffffu, v, 1);                          \
        float u  = kh ? fF : fO;                                                \
        float ur = __shfl_xor_sync(0xffffffffu, u, 1);                          \
        float p1 = ((kh ? fG : fI) + vr) + in1;                                 \
        float p2 = ((kh ? fO : fF) + ur) + in2;                                 \
        float y1 = fmaf(my1, ftanh_(m1 * p1), a1);       /* kh0: si ; kh1: tg */\
        float y2 = fmaf(0.5f, ftanh_(0.5f * p2), 0.5f);  /* kh0: sf ; kh1: so */\
        float tg_ = __shfl_xor_sync(0xffffffffu, y1, 1);                        \
        float so_ = __shfl_xor_sync(0xffffffffu, y2, 1);                        \
        cc[s] = y2 * cc[s] + y1 * tg_;                   /* valid on kh0 */     \
        float hVal = so_ * ftanh_(cc[s]);                                       \
        if (!kh) hspF[s][e] = hVal;                                             \
    }                                                                           \
} while (0)

#define PHASE4(SQ, T) do {                                                      \
    float2 hv = ((const float2*)hspF[SQ])[lane];                                \
    float part = fmaf(hv.x, wo0, hv.y * wo1);                                   \
    _Pragma("unroll")                                                           \
    for (int o = 16; o; o >>= 1)                                                \
        part += __shfl_xor_sync(0xffffffffu, part, o);                          \
    float raw = fsig(part + bo);                                                \
    float pay = paysh[SQ][T];                                                   \
    float adj = ((T) == 0) ? raw : raw * nd;                                    \
    lossAcc += (double)(adj * pay);                                             \
    if ((T) < CHUNK - 1) nd *= (1.0f - raw);                                    \
} while (0)

    for (int ch = 0; ch < nch; ++ch) {
        __syncthreads();  // previous chunk fully consumed (incl. phase4_B(127))
        // ---- chunk preamble ----
        for (int i = tid; i < SEQS * CHUNK; i += NTHR) {
            int s  = i >> 7;
            int tt = i & (CHUNK - 1);
            int b  = baseSh[s] + ch * CHUNK;
            float2 pv = ((const float2*)p)[b + tt];
            float2 pz = ((const float2*)p)[b];
            float x0 = pv.x - pz.x, x1 = pv.y - pz.y;
            xsh[s][tt][0] = pk2(x0, x0);
            xsh[s][tt][1] = pk2(x1, x1);
            paysh[s][tt] = opwSh[s] * ((__logf(pv.x) - olpSh[s].x) + (__logf(pv.y) - olpSh[s].y));
        }
        __syncthreads();

        // prime both pair matvecs for t=0 (reads h from init / previous chunk)
        MATVEC(accA, 0);
        MATVEC(accB, 2);

        #pragma unroll 1
        for (int t = 0; t < CHUNK; ++t) {
            GATES(accA, 0, t);            // publish h_A(t)
            __syncthreads();              // barX
            if (t < CHUNK - 1) MATVEC(accA, 0);   // mA(t+1): reads h_A(t)
            if (wpair == 0) PHASE4(w, t);         // seqs 0,1: read h_A(t), pre-barY
            GATES(accB, 2, t);            // publish h_B(t)
            __syncthreads();              // barY
            if (t < CHUNK - 1) MATVEC(accB, 2);   // mB(t+1): reads h_B(t)
            if (wpair == 1) PHASE4(w, t);         // seqs 2,3: read h_B(t), pre-barX'
        }
    }

    if (lane == 0) atomicAdd(out, (float)lossAcc);

#undef MATVEC
#undef GATES
#undef PHASE4
}

extern "C" void kernel_launch(void* const* d_in, const int* in_sizes, int n_in,
                              void* d_out, int out_size)
{
    const int*   inds        = (const int*)  d_in[0];
    const float* p           = (const float*)d_in[1];
    const float* ls_probs    = (const float*)d_in[2];
    const float* open_probs  = (const float*)d_in[3];
    const int*   open_slices = (const int*)  d_in[4];
    const float* open_hx     = (const float*)d_in[5];
    const float* W_ih        = (const float*)d_in[6];
    const float* W_hh        = (const float*)d_in[7];
    const float* b_ih        = (const float*)d_in[8];
    const float* b_hh        = (const float*)d_in[9];
    const float* W_out       = (const float*)d_in[10];
    const float* b_out       = (const float*)d_in[11];
    const int*   n_chunks    = (n_in > 12) ? (const int*)d_in[12] : nullptr;

    float* out = (float*)d_out;

    pc_zero_kernel<<<1, 32>>>(out);
    pc_lstm_kernel<<<NBLK, NTHR>>>(inds, p, ls_probs, open_probs, open_slices,
                                   open_hx, W_ih, W_hh, b_ih, b_hh,
                                   W_out, b_out, n_chunks, out);
}

// round 14
// speedup vs baseline: 1.5810x; 1.3298x over previous
#include <cuda_runtime.h>
#include <cstdint>

#define HID   64
#define CHUNK 128
#define SEQS  4      // sequences per CTA
#define NTHR  128    // thread = (e, kh): 64 elements x 2 k-halves
#define NBLK  256    // 256 * 4 = 1024 sequences

typedef unsigned long long ull;

__device__ __forceinline__ ull pk2(float a, float b) {
    ull r; asm("mov.b64 %0, {%1, %2};" : "=l"(r) : "f"(a), "f"(b)); return r;
}
__device__ __forceinline__ void upk2(ull v, float &a, float &b) {
    asm("mov.b64 {%0, %1}, %2;" : "=f"(a), "=f"(b) : "l"(v));
}
__device__ __forceinline__ ull ffma2(ull a, ull b, ull c) {
    ull d; asm("fma.rn.f32x2 %0, %1, %2, %3;" : "=l"(d) : "l"(a), "l"(b), "l"(c)); return d;
}
// single-MUFU tanh (sm_75+): MUFU.TANH
__device__ __forceinline__ float ftanh_(float x){
    float y; asm("tanh.approx.f32 %0, %1;" : "=f"(y) : "f"(x)); return y;
}
// sigmoid(x) = 0.5*tanh(0.5x) + 0.5
__device__ __forceinline__ float fsig(float x){
    return fmaf(0.5f, ftanh_(0.5f * x), 0.5f);
}

__global__ void pc_zero_kernel(float* o) { if (threadIdx.x == 0) o[0] = 0.0f; }

__global__ void __launch_bounds__(NTHR, 2)
pc_lstm_kernel(const int*   __restrict__ inds,
               const float* __restrict__ p,
               const float* __restrict__ ls_probs,
               const float* __restrict__ open_probs,
               const int*   __restrict__ open_slices,
               const float* __restrict__ open_hx,
               const float* __restrict__ W_ih,
               const float* __restrict__ W_hh,
               const float* __restrict__ b_ih,
               const float* __restrict__ b_hh,
               const float* __restrict__ W_out,
               const float* __restrict__ b_out,
               const int*   __restrict__ n_chunks_ptr,
               float*       __restrict__ out)
{
    __shared__ __align__(16) float hspF[2][SEQS][HID];     // double-buffered h
    __shared__ __align__(16) ull   xsh[SEQS][CHUNK][2];    // splatted (x0,x0),(x1,x1)
    __shared__ float  paysh[SEQS][CHUNK];
    __shared__ float  rawb[SEQS][CHUNK];                   // pre-sigmoid dots
    __shared__ float  opwSh[SEQS];
    __shared__ float2 olpSh[SEQS];
    __shared__ int    baseSh[SEQS];

    // one-time anti-phase skew for co-resident CTA pairs
    if (blockIdx.x & 1) __nanosleep(2000);

    const int tid  = threadIdx.x;
    const int e    = tid >> 1;        // element 0..63
    const int kh   = tid & 1;         // k-half
    const int kb   = kh * 32;         // k base
    const int kh4  = kh << 2;         // XOR constant: bank-spread iteration order
    const int w    = tid >> 5;        // warp 0..3 <-> seq w in phase 4
    const int lane = tid & 31;

    const int rI = e, rF = 64 + e, rG = 128 + e, rO = 192 + e;

    // ---- W_hh: 4 rows x 32 k-values (k-half), k-pair packed, bank-spread ----
    ull wI[16], wF[16], wG[16], wO[16];
    #pragma unroll
    for (int i = 0; i < 8; ++i) {
        int kf = kb + 4 * (i ^ kh4);
        wI[2*i]   = pk2(W_hh[rI * HID + kf],     W_hh[rI * HID + kf + 1]);
        wI[2*i+1] = pk2(W_hh[rI * HID + kf + 2], W_hh[rI * HID + kf + 3]);
        wF[2*i]   = pk2(W_hh[rF * HID + kf],     W_hh[rF * HID + kf + 1]);
        wF[2*i+1] = pk2(W_hh[rF * HID + kf + 2], W_hh[rF * HID + kf + 3]);
        wG[2*i]   = pk2(W_hh[rG * HID + kf],     W_hh[rG * HID + kf + 1]);
        wG[2*i+1] = pk2(W_hh[rG * HID + kf + 2], W_hh[rG * HID + kf + 3]);
        wO[2*i]   = pk2(W_hh[rO * HID + kf],     W_hh[rO * HID + kf + 1]);
        wO[2*i+1] = pk2(W_hh[rO * HID + kf + 2], W_hh[rO * HID + kf + 3]);
    }

    const ull biasIF = pk2(b_ih[rI] + b_hh[rI], b_ih[rF] + b_hh[rF]);
    const ull biasGO = pk2(b_ih[rG] + b_hh[rG], b_ih[rO] + b_hh[rO]);
    const ull wIF0 = pk2(W_ih[rI*2],   W_ih[rF*2]);
    const ull wIF1 = pk2(W_ih[rI*2+1], W_ih[rF*2+1]);
    const ull wGO0 = pk2(W_ih[rG*2],   W_ih[rO*2]);
    const ull wGO1 = pk2(W_ih[rG*2+1], W_ih[rO*2+1]);

    const float wo0 = W_out[2 * lane];
    const float wo1 = W_out[2 * lane + 1];
    const float bo  = b_out[0];

    if (tid < SEQS) {
        int q = blockIdx.x * SEQS + tid;
        baseSh[tid] = inds[q >> 4] + (q & 15);   // B2 == 16
        int sl = open_slices[q];
        olpSh[tid] = make_float2(__logf(p[2 * sl]), __logf(p[2 * sl + 1]));
        opwSh[tid] = open_probs[q] * (2.0f * ls_probs[q] - 1.0f);
    }

    // init c (both kh threads, identical) and h (kh==0 publishes)
    float cc[SEQS];
    #pragma unroll
    for (int s = 0; s < SEQS; ++s) {
        int q = blockIdx.x * SEQS + s;
        cc[s] = open_hx[(q * 2 + 1) * HID + e];
        if (!kh) hspF[0][s][e] = open_hx[(q * 2 + 0) * HID + e];
    }
    __syncthreads();

    const int nch = n_chunks_ptr ? n_chunks_ptr[0] : 128;

    float  ndc = 1.0f;           // survival carry (per warp == per seq, all lanes)
    double lossAcc = 0.0;        // per-lane; DADD only once per chunk
    int    cur = 0;              // even #steps/chunk -> cur==0 at chunk starts

    for (int ch = 0; ch < nch; ++ch) {
        __syncthreads();  // previous chunk's xsh/paysh/rawb fully consumed
        // ---- chunk preamble ----
        for (int i = tid; i < SEQS * CHUNK; i += NTHR) {
            int s  = i >> 7;
            int tt = i & (CHUNK - 1);
            int b  = baseSh[s] + ch * CHUNK;
            float2 pv = ((const float2*)p)[b + tt];
            float2 pz = ((const float2*)p)[b];
            float x0 = pv.x - pz.x, x1 = pv.y - pz.y;
            xsh[s][tt][0] = pk2(x0, x0);
            xsh[s][tt][1] = pk2(x1, x1);
            paysh[s][tt] = opwSh[s] * ((__logf(pv.x) - olpSh[s].x) + (__logf(pv.y) - olpSh[s].y));
        }
        __syncthreads();

        #pragma unroll 1
        for (int t = 0; t < CHUNK; ++t) {
            // ---- lagged phase-4 h read (h after step t-1) ----
            float2 hv;
            if (t) hv = ((const float2*)hspF[cur][w])[lane];

            // ---- input terms, gate-pair packed ----
            ull accI_[SEQS], accG_[SEQS];
            #pragma unroll
            for (int s = 0; s < SEQS; ++s) {
                ulonglong2 xv = *(const ulonglong2*)&xsh[s][t][0];
                accI_[s] = ffma2(wIF1, xv.y, ffma2(wIF0, xv.x, biasIF));
                accG_[s] = ffma2(wGO1, xv.y, ffma2(wGO0, xv.x, biasGO));
            }

            // ---- matvec: 4 rows x k-half x 4 seqs; 1 LDS.128 -> 8 FFMA2 ----
            ull accI[SEQS], accF[SEQS], accG[SEQS], accO[SEQS];
            #pragma unroll
            for (int s = 0; s < SEQS; ++s) { accI[s]=0; accF[s]=0; accG[s]=0; accO[s]=0; }
            #pragma unroll
            for (int i = 0; i < 8; ++i) {
                int kf = kb + 4 * (i ^ kh4);     // bank-spread order for kh=1
                #pragma unroll
                for (int s = 0; s < SEQS; ++s) {
                    ulonglong2 hh = *(const ulonglong2*)&hspF[cur][s][kf];
                    accI[s] = ffma2(wI[2*i], hh.x, accI[s]);
                    accF[s] = ffma2(wF[2*i], hh.x, accF[s]);
                    accG[s] = ffma2(wG[2*i], hh.x, accG[s]);
                    accO[s] = ffma2(wO[2*i], hh.x, accO[s]);
                    accI[s] = ffma2(wI[2*i+1], hh.y, accI[s]);
                    accF[s] = ffma2(wF[2*i+1], hh.y, accF[s]);
                    accG[s] = ffma2(wG[2*i+1], hh.y, accG[s]);
                    accO[s] = ffma2(wO[2*i+1], hh.y, accO[s]);
                }
            }

            // ---- lagged phase-4-lite (step t-1): dot + butterfly + 1 STS ----
            if (t) {
                float part = fmaf(hv.x, wo0, hv.y * wo1);
                #pragma unroll
                for (int o = 16; o; o >>= 1)
                    part += __shfl_xor_sync(0xffffffffu, part, o);
                if (lane == 0) rawb[w][t - 1] = part;
            }

            // ---- fold, k-half combine, split-MUFU gates, c/h update ----
            #pragma unroll
            for (int s = 0; s < SEQS; ++s) {
                float lo, hi;
                upk2(accI[s], lo, hi); float fIv = lo + hi;
                upk2(accF[s], lo, hi); float fFv = lo + hi;
                upk2(accG[s], lo, hi); float fGv = lo + hi;
                upk2(accO[s], lo, hi); float fOv = lo + hi;
                fIv += __shfl_xor_sync(0xffffffffu, fIv, 1);   // combine k-halves
                fFv += __shfl_xor_sync(0xffffffffu, fFv, 1);
                fGv += __shfl_xor_sync(0xffffffffu, fGv, 1);
                fOv += __shfl_xor_sync(0xffffffffu, fOv, 1);
                float inI, inF, inG, inO;
                upk2(accI_[s], inI, inF);
                upk2(accG_[s], inG, inO);
                float pI = fIv + inI, pF = fFv + inF;
                float pG = fGv + inG, pO = fOv + inO;

                // split MUFU across the kh pair (all via MUFU.TANH):
                float u1 = kh ? pG : 0.5f * pI;
                float r1 = ftanh_(u1);
                float g1 = kh ? r1 : fmaf(0.5f, r1, 0.5f);     // kh0: si, kh1: tg
                float u2 = 0.5f * (kh ? pO : pF);
                float g2 = fmaf(0.5f, ftanh_(u2), 0.5f);       // kh0: sf, kh1: so
                float x1 = __shfl_xor_sync(0xffffffffu, g1, 1);
                float x2 = __shfl_xor_sync(0xffffffffu, g2, 1);
                float si = kh ? x1 : g1;
                float tg = kh ? g1 : x1;
                float sf = kh ? x2 : g2;
                float so = kh ? g2 : x2;
                cc[s] = sf * cc[s] + si * tg;
                if (!kh) hspF[cur ^ 1][s][e] = so * ftanh_(cc[s]);
            }
            __syncthreads();   // single barrier: h published, buffers rotate
            cur ^= 1;
        }

        // ---- trailing dot for t = CHUNK-1 ----
        {
            float2 hv = ((const float2*)hspF[cur][w])[lane];
            float part = fmaf(hv.x, wo0, hv.y * wo1);
            #pragma unroll
            for (int o = 16; o; o >>= 1)
                part += __shfl_xor_sync(0xffffffffu, part, o);
            if (lane == 0) rawb[w][CHUNK - 1] = part;
        }
        __syncwarp();

        // ---- chunk-end: vectorized survival chain + loss (exact semantics) ----
        {
            const int t0 = 4 * lane;
            float raw0 = fsig(rawb[w][t0 + 0] + bo);
            float raw1 = fsig(rawb[w][t0 + 1] + bo);
            float raw2 = fsig(rawb[w][t0 + 2] + bo);
            float raw3 = fsig(rawb[w][t0 + 3] + bo);
            float m0 = 1.0f - raw0, m1 = 1.0f - raw1;
            float m2 = 1.0f - raw2, m3 = 1.0f - raw3;
            float P1 = m0, P2 = m0 * m1, P3 = P2 * m2;
            float Pl = P3 * m3;
            // inclusive multiplicative scan over lane-local products
            float incl = Pl;
            #pragma unroll
            for (int o = 1; o < 32; o <<= 1) {
                float v = __shfl_up_sync(0xffffffffu, incl, o);
                if (lane >= o) incl *= v;
            }
            float E = __shfl_up_sync(0xffffffffu, incl, 1);
            if (lane == 0) E = 1.0f;
            float basep = ndc * E;
            float nd0 = (lane == 0) ? 1.0f : basep;   // t==0 bypasses carry
            float nd1 = basep * P1;
            float nd2 = basep * P2;
            float nd3 = basep * P3;
            float ls = raw0 * nd0 * paysh[w][t0 + 0]
                     + raw1 * nd1 * paysh[w][t0 + 1]
                     + raw2 * nd2 * paysh[w][t0 + 2]
                     + raw3 * nd3 * paysh[w][t0 + 3];
            lossAcc += (double)ls;
            // carry: prod_{u<=126}(1-raw(u)) = E(31)*P3(31)  (excludes t=127)
            float carry = __shfl_sync(0xffffffffu, E * P3, 31);
            ndc *= carry;
        }
    }

    // final: reduce per-lane loss partials within warp, one atomic per warp
    #pragma unroll
    for (int o = 16; o; o >>= 1)
        lossAcc += __shfl_xor_sync(0xffffffffu, lossAcc, o);
    if (lane == 0) atomicAdd(out, (float)lossAcc);
}

extern "C" void kernel_launch(void* const* d_in, const int* in_sizes, int n_in,
                              void* d_out, int out_size)
{
    const int*   inds        = (const int*)  d_in[0];
    const float* p           = (const float*)d_in[1];
    const float* ls_probs    = (const float*)d_in[2];
    const float* open_probs  = (const float*)d_in[3];
    const int*   open_slices = (const int*)  d_in[4];
    const float* open_hx     = (const float*)d_in[5];
    const float* W_ih        = (const float*)d_in[6];
    const float* W_hh        = (const float*)d_in[7];
    const float* b_ih        = (const float*)d_in[8];
    const float* b_hh        = (const float*)d_in[9];
    const float* W_out       = (const float*)d_in[10];
    const float* b_out       = (const float*)d_in[11];
    const int*   n_chunks    = (n_in > 12) ? (const int*)d_in[12] : nullptr;

    float* out = (float*)d_out;

    pc_zero_kernel<<<1, 32>>>(out);
    pc_lstm_kernel<<<NBLK, NTHR>>>(inds, p, ls_probs, open_probs, open_slices,
                                   open_hx, W_ih, W_hh, b_ih, b_hh,
                                   W_out, b_out, n_chunks, out);
}